// round 8
// baseline (speedup 1.0000x reference)
#include <cuda_runtime.h>
#include <cstdint>
#include <cstddef>

// Problem shape (fixed by setup_inputs)
#define B_DIM 8192
#define D_DIM 4096
#define H_DIM 8192
#define C_DIM 1000
#define C_PAD 1024

// ACL arm_gemm GemmHybrid fp32 (6x16) K-blocking on Grace (L1d = 64 KB):
// k_block = (L1/2)/(4*16) = 512; evened across K: 4096=8*512, 8192=16*512.
#define KC 512
#define KC_TILES (KC / 8)   // fold period in BK=8 tiles

// ---------------- scratch (static device arrays; no runtime allocation) ----
__device__ float g_w1q[(size_t)H_DIM * D_DIM];   // 128 MB  fl(q*scale) weights
__device__ float g_w2q[(size_t)H_DIM * H_DIM];   // 256 MB
__device__ float g_w3q[(size_t)H_DIM * H_DIM];   // 256 MB
__device__ float g_w4q[(size_t)C_PAD * H_DIM];   //  32 MB (rows 1000..1023 zero)
__device__ float g_h1 [(size_t)B_DIM * H_DIM];   // 256 MB (float activations)
__device__ float g_h2 [(size_t)B_DIM * H_DIM];   // 256 MB
__device__ unsigned g_absmax[4];

// ---------------- absmax reduction (per weight tensor) ---------------------
__global__ void k_zero_absmax() {
    if (threadIdx.x < 4) g_absmax[threadIdx.x] = 0u;
}

__global__ void __launch_bounds__(256) k_absmax(const float* __restrict__ w,
                                                size_t n, int idx) {
    __shared__ unsigned sm[256];
    unsigned m = 0u;
    size_t stride = (size_t)gridDim.x * blockDim.x;
    for (size_t i = (size_t)blockIdx.x * blockDim.x + threadIdx.x; i < n; i += stride) {
        unsigned b = __float_as_uint(fabsf(w[i]));  // abs-float bit order == value order
        m = m > b ? m : b;
    }
    sm[threadIdx.x] = m;
    __syncthreads();
    for (int s = 128; s > 0; s >>= 1) {
        if (threadIdx.x < (unsigned)s) {
            unsigned o = sm[threadIdx.x + s];
            if (o > sm[threadIdx.x]) sm[threadIdx.x] = o;
        }
        __syncthreads();
    }
    if (threadIdx.x == 0) atomicMax(&g_absmax[idx], sm[0]);
}

// ---------------- weight quantization: fl(round(clip(w/s,-3,3)) * s) -------
// Bit-matches the fp32 reference quantizer: IEEE RN div/mul, rintf=half-even
// (= jnp.round). Pads [n_real, n_total) with 0.
__global__ void __launch_bounds__(256) k_quant(const float* __restrict__ w,
                                               float* __restrict__ q,
                                               size_t n_real, size_t n_total,
                                               int idx) {
    float scale = __fdiv_rn(__uint_as_float(g_absmax[idx]), 3.0f);
    size_t stride = (size_t)gridDim.x * blockDim.x;
    for (size_t i = (size_t)blockIdx.x * blockDim.x + threadIdx.x; i < n_total; i += stride) {
        float v = 0.0f;
        if (i < n_real) {
            float t = __fdiv_rn(w[i], scale);
            t = fminf(fmaxf(t, -3.0f), 3.0f);
            v = __fmul_rn(rintf(t), scale);
        }
        q[i] = v;
    }
}

// ---------------- ACL-hybrid-order GEMM -------------------------------------
// Per output element: K split into KC=512 panels; within a panel the partial
// sum is a serial ascending fp32 FMA chain from 0; panels folded sequentially
// C = (((S0) + S1) + S2)... with one fp32 add each (first block = beta-0
// write == add to 0). BK=8 tiles (512 = 64*8). cur in regs, C in shared.
// EPI 0: quant_relu((C*bns+bnb)) -> float h (stride H_DIM)
// EPI 1: raw C -> out (stride C_DIM, masked n < C_DIM)
template <int EPI>
__global__ void __launch_bounds__(256) k_gemm(const float* __restrict__ A,
                                              const float* __restrict__ Bw,
                                              int K,
                                              float* __restrict__ outF,
                                              const float* __restrict__ bns,
                                              const float* __restrict__ bnb,
                                              const float* __restrict__ act_s) {
    extern __shared__ float smdyn[];
    float (*As)[128] = reinterpret_cast<float(*)[128]>(smdyn);            // [8][128]
    float (*Bs)[128] = reinterpret_cast<float(*)[128]>(smdyn + 8 * 128);  // [8][128]
    float* Csm       = smdyn + 2 * 8 * 128;                               // [64][256]

    int bn0 = blockIdx.x * 128;
    int bm0 = blockIdx.y * 128;
    int tid = threadIdx.x;
    int tm = (tid >> 4) << 3;   // 0,8,..,120
    int tn = (tid & 15) << 3;

    float cur[8][8];
#pragma unroll
    for (int i = 0; i < 8; i++)
#pragma unroll
        for (int j = 0; j < 8; j++) cur[i][j] = 0.0f;
#pragma unroll
    for (int e = 0; e < 64; e++) Csm[e * 256 + tid] = 0.0f;

    int lr = tid >> 1;          // 0..127 (row within tile)
    int lc = (tid & 1) * 4;     // 0 or 4 (col within 8-wide K slab)

    int nt = K / 8;
    for (int t = 0; t < nt; t++) {
        int k0 = t * 8;
        {
            float4 v = *reinterpret_cast<const float4*>(
                A + (size_t)(bm0 + lr) * K + k0 + lc);
            As[lc + 0][lr] = v.x; As[lc + 1][lr] = v.y;
            As[lc + 2][lr] = v.z; As[lc + 3][lr] = v.w;
        }
        {
            float4 v = *reinterpret_cast<const float4*>(
                Bw + (size_t)(bn0 + lr) * K + k0 + lc);
            Bs[lc + 0][lr] = v.x; Bs[lc + 1][lr] = v.y;
            Bs[lc + 2][lr] = v.z; Bs[lc + 3][lr] = v.w;
        }
        __syncthreads();
#pragma unroll
        for (int k = 0; k < 8; k++) {   // ascending k: serial dependent FMA chain
            float a[8], b[8];
            *reinterpret_cast<float4*>(a)     = *reinterpret_cast<const float4*>(&As[k][tm]);
            *reinterpret_cast<float4*>(a + 4) = *reinterpret_cast<const float4*>(&As[k][tm + 4]);
            *reinterpret_cast<float4*>(b)     = *reinterpret_cast<const float4*>(&Bs[k][tn]);
            *reinterpret_cast<float4*>(b + 4) = *reinterpret_cast<const float4*>(&Bs[k][tn + 4]);
#pragma unroll
            for (int i = 0; i < 8; i++)
#pragma unroll
                for (int j = 0; j < 8; j++) cur[i][j] = fmaf(a[i], b[j], cur[i][j]);
        }
        __syncthreads();
        if (((t + 1) % KC_TILES) == 0) {   // panel boundary: fold partial into C
#pragma unroll
            for (int i = 0; i < 8; i++)
#pragma unroll
                for (int j = 0; j < 8; j++) {
                    int e = i * 8 + j;
                    Csm[e * 256 + tid] = __fadd_rn(Csm[e * 256 + tid], cur[i][j]);
                    cur[i][j] = 0.0f;
                }
        }
    }
    // final (possibly partial) panel fold — exact no-op if cur == 0
#pragma unroll
    for (int i = 0; i < 8; i++)
#pragma unroll
        for (int j = 0; j < 8; j++) {
            int e = i * 8 + j;
            Csm[e * 256 + tid] = __fadd_rn(Csm[e * 256 + tid], cur[i][j]);
        }

    if (EPI == 0) {
        float as = act_s[0];
        float bsv[8], bbv[8];
#pragma unroll
        for (int j = 0; j < 8; j++) {
            bsv[j] = bns[bn0 + tn + j];
            bbv[j] = bnb[bn0 + tn + j];
        }
#pragma unroll
        for (int i = 0; i < 8; i++) {
            float pk[8];
#pragma unroll
            for (int j = 0; j < 8; j++) {
                float c   = Csm[(i * 8 + j) * 256 + tid];
                float m   = __fmul_rn(c, bsv[j]);
                float pre = __fadd_rn(m, bbv[j]);
                float t   = __fdiv_rn(fmaxf(pre, 0.0f), as);
                t = fminf(fmaxf(t, 0.0f), 15.0f);
                pk[j] = __fmul_rn(rintf(t), as);
            }
            float4* dst = reinterpret_cast<float4*>(
                outF + (size_t)(bm0 + tm + i) * H_DIM + bn0 + tn);
            dst[0] = *reinterpret_cast<const float4*>(pk);
            dst[1] = *reinterpret_cast<const float4*>(pk + 4);
        }
    } else {
#pragma unroll
        for (int i = 0; i < 8; i++) {
            size_t row = (size_t)(bm0 + tm + i);
#pragma unroll
            for (int j = 0; j < 8; j++) {
                int col = bn0 + tn + j;
                if (col < C_DIM) outF[row * C_DIM + col] = Csm[(i * 8 + j) * 256 + tid];
            }
        }
    }
}

// ---------------- launch --------------------------------------------------
extern "C" void kernel_launch(void* const* d_in, const int* in_sizes, int n_in,
                              void* d_out, int out_size) {
    (void)in_sizes; (void)n_in; (void)out_size;
    const float* x    = (const float*)d_in[0];
    const float* w1   = (const float*)d_in[1];
    const float* w2   = (const float*)d_in[2];
    const float* w3   = (const float*)d_in[3];
    const float* w4   = (const float*)d_in[4];
    const float* bns1 = (const float*)d_in[5];
    const float* bnb1 = (const float*)d_in[6];
    const float* bns2 = (const float*)d_in[7];
    const float* bnb2 = (const float*)d_in[8];
    const float* bns3 = (const float*)d_in[9];
    const float* bnb3 = (const float*)d_in[10];
    const float* as1  = (const float*)d_in[11];
    const float* as2  = (const float*)d_in[12];
    const float* as3  = (const float*)d_in[13];
    float* out = (float*)d_out;

    float *w1q, *w2q, *w3q, *w4q, *h1, *h2;
    cudaGetSymbolAddress((void**)&w1q, g_w1q);
    cudaGetSymbolAddress((void**)&w2q, g_w2q);
    cudaGetSymbolAddress((void**)&w3q, g_w3q);
    cudaGetSymbolAddress((void**)&w4q, g_w4q);
    cudaGetSymbolAddress((void**)&h1,  g_h1);
    cudaGetSymbolAddress((void**)&h2,  g_h2);

    const int SMEM = (2 * 8 * 128 + 64 * 256) * sizeof(float);  // 72 KB
    cudaFuncSetAttribute(k_gemm<0>, cudaFuncAttributeMaxDynamicSharedMemorySize, SMEM);
    cudaFuncSetAttribute(k_gemm<1>, cudaFuncAttributeMaxDynamicSharedMemorySize, SMEM);

    k_zero_absmax<<<1, 32>>>();
    k_absmax<<<1024, 256>>>(w1, (size_t)H_DIM * D_DIM, 0);
    k_absmax<<<1024, 256>>>(w2, (size_t)H_DIM * H_DIM, 1);
    k_absmax<<<1024, 256>>>(w3, (size_t)H_DIM * H_DIM, 2);
    k_absmax<<<1024, 256>>>(w4, (size_t)C_DIM * H_DIM, 3);

    k_quant<<<4096, 256>>>(w1, w1q, (size_t)H_DIM * D_DIM, (size_t)H_DIM * D_DIM, 0);
    k_quant<<<8192, 256>>>(w2, w2q, (size_t)H_DIM * H_DIM, (size_t)H_DIM * H_DIM, 1);
    k_quant<<<8192, 256>>>(w3, w3q, (size_t)H_DIM * H_DIM, (size_t)H_DIM * H_DIM, 2);
    k_quant<<<2048, 256>>>(w4, w4q, (size_t)C_DIM * H_DIM, (size_t)C_PAD * H_DIM, 3);

    dim3 gHH(H_DIM / 128, B_DIM / 128);
    dim3 gC (C_PAD / 128, B_DIM / 128);
    k_gemm<0><<<gHH, 256, SMEM>>>(x,  w1q, D_DIM, h1,  bns1, bnb1, as1);
    k_gemm<0><<<gHH, 256, SMEM>>>(h1, w2q, H_DIM, h2,  bns2, bnb2, as2);
    k_gemm<0><<<gHH, 256, SMEM>>>(h2, w3q, H_DIM, h1,  bns3, bnb3, as3);
    k_gemm<1><<<gC,  256, SMEM>>>(h1, w4q, H_DIM, out, nullptr, nullptr, nullptr);
}

// round 9
// speedup vs baseline: 1.1464x; 1.1464x over previous
#include <cuda_runtime.h>
#include <cstdint>
#include <cstddef>

// Problem shape (fixed by setup_inputs)
#define B_DIM 8192
#define D_DIM 4096
#define H_DIM 8192
#define C_DIM 1000
#define C_PAD 1024

// ACL arm_gemm GemmHybrid fp32 K-blocking (verified PASS R7): KC = 512.
#define KC 512
#define BK 16
#define KC_TILES (KC / BK)   // fold period in BK=16 tiles

typedef unsigned long long u64;

// ---- packed dual-fp32 FMA (sm_100+): per-lane IEEE RN fp32 FMA -------------
__device__ __forceinline__ u64 pack2(float lo, float hi) {
    u64 r;
    asm("mov.b64 %0, {%1, %2};" : "=l"(r) : "f"(lo), "f"(hi));
    return r;
}
__device__ __forceinline__ void unpack2(u64 v, float& lo, float& hi) {
    asm("mov.b64 {%0, %1}, %2;" : "=f"(lo), "=f"(hi) : "l"(v));
}
__device__ __forceinline__ void fma2(u64& d, u64 a, u64 b, u64 c) {
    asm("fma.rn.f32x2 %0, %1, %2, %3;" : "=l"(d) : "l"(a), "l"(b), "l"(c));
}

// ---------------- scratch (static device arrays; no runtime allocation) ----
__device__ float g_w1q[(size_t)H_DIM * D_DIM];   // 128 MB  fl(q*scale) weights
__device__ float g_w2q[(size_t)H_DIM * H_DIM];   // 256 MB
__device__ float g_w3q[(size_t)H_DIM * H_DIM];   // 256 MB
__device__ float g_w4q[(size_t)C_PAD * H_DIM];   //  32 MB (rows 1000..1023 zero)
__device__ float g_h1 [(size_t)B_DIM * H_DIM];   // 256 MB (float activations)
__device__ float g_h2 [(size_t)B_DIM * H_DIM];   // 256 MB
__device__ unsigned g_absmax[4];

// ---------------- absmax reduction (per weight tensor) ---------------------
__global__ void k_zero_absmax() {
    if (threadIdx.x < 4) g_absmax[threadIdx.x] = 0u;
}

__global__ void __launch_bounds__(256) k_absmax(const float* __restrict__ w,
                                                size_t n, int idx) {
    __shared__ unsigned sm[256];
    unsigned m = 0u;
    size_t stride = (size_t)gridDim.x * blockDim.x;
    for (size_t i = (size_t)blockIdx.x * blockDim.x + threadIdx.x; i < n; i += stride) {
        unsigned b = __float_as_uint(fabsf(w[i]));  // abs-float bit order == value order
        m = m > b ? m : b;
    }
    sm[threadIdx.x] = m;
    __syncthreads();
    for (int s = 128; s > 0; s >>= 1) {
        if (threadIdx.x < (unsigned)s) {
            unsigned o = sm[threadIdx.x + s];
            if (o > sm[threadIdx.x]) sm[threadIdx.x] = o;
        }
        __syncthreads();
    }
    if (threadIdx.x == 0) atomicMax(&g_absmax[idx], sm[0]);
}

// ---------------- weight quantization: fl(round(clip(w/s,-3,3)) * s) -------
// Bit-matches the fp32 reference quantizer: IEEE RN div/mul, rintf=half-even
// (= jnp.round). Pads [n_real, n_total) with 0.
__global__ void __launch_bounds__(256) k_quant(const float* __restrict__ w,
                                               float* __restrict__ q,
                                               size_t n_real, size_t n_total,
                                               int idx) {
    float scale = __fdiv_rn(__uint_as_float(g_absmax[idx]), 3.0f);
    size_t stride = (size_t)gridDim.x * blockDim.x;
    for (size_t i = (size_t)blockIdx.x * blockDim.x + threadIdx.x; i < n_total; i += stride) {
        float v = 0.0f;
        if (i < n_real) {
            float t = __fdiv_rn(w[i], scale);
            t = fminf(fmaxf(t, -3.0f), 3.0f);
            v = __fmul_rn(rintf(t), scale);
        }
        q[i] = v;
    }
}

// ---------------- ACL-hybrid-order GEMM, FFMA2 engine -----------------------
// Numerics contract (verified PASS): per output element, K split into KC=512
// panels; within a panel a serial ascending fp32 FMA chain from 0; panels
// folded sequentially with one fp32 add each. FFMA2 lanes are independent
// per-element chains (pair over adjacent j) — bit-identical to scalar FFMA.
// EPI 0: quant_relu((C*bns+bnb)) -> float h (stride H_DIM)
// EPI 1: raw C -> out (stride C_DIM, masked n < C_DIM)
template <int EPI>
__global__ void __launch_bounds__(256) k_gemm(const float* __restrict__ A,
                                              const float* __restrict__ Bw,
                                              int K,
                                              float* __restrict__ outF,
                                              const float* __restrict__ bns,
                                              const float* __restrict__ bnb,
                                              const float* __restrict__ act_s) {
    extern __shared__ float smdyn[];
    float (*As)[128] = reinterpret_cast<float(*)[128]>(smdyn);              // [BK][128]
    float (*Bs)[128] = reinterpret_cast<float(*)[128]>(smdyn + BK * 128);   // [BK][128]
    float* Csm       = smdyn + 2 * BK * 128;                                // [64][256]

    int bn0 = blockIdx.x * 128;
    int bm0 = blockIdx.y * 128;
    int tid = threadIdx.x;
    int tm = (tid >> 4) << 3;   // 0,8,..,120
    int tn = (tid & 15) << 3;

    u64 acc2[8][4];             // acc2[i][j2] = (acc[i][2j2], acc[i][2j2+1])
#pragma unroll
    for (int i = 0; i < 8; i++)
#pragma unroll
        for (int j2 = 0; j2 < 4; j2++) acc2[i][j2] = 0ull;
#pragma unroll
    for (int e = 0; e < 64; e++) Csm[e * 256 + tid] = 0.0f;

    int lr = tid >> 1;          // 0..127 (row within tile)
    int lc = (tid & 1) * 8;     // 0 or 8 (col within BK=16 K slab)

    int nt = K / BK;
    for (int t = 0; t < nt; t++) {
        int k0 = t * BK;
        {
            const float4* src = reinterpret_cast<const float4*>(
                A + (size_t)(bm0 + lr) * K + k0 + lc);
            float4 v0 = src[0], v1 = src[1];
            As[lc + 0][lr] = v0.x; As[lc + 1][lr] = v0.y;
            As[lc + 2][lr] = v0.z; As[lc + 3][lr] = v0.w;
            As[lc + 4][lr] = v1.x; As[lc + 5][lr] = v1.y;
            As[lc + 6][lr] = v1.z; As[lc + 7][lr] = v1.w;
        }
        {
            const float4* src = reinterpret_cast<const float4*>(
                Bw + (size_t)(bn0 + lr) * K + k0 + lc);
            float4 v0 = src[0], v1 = src[1];
            Bs[lc + 0][lr] = v0.x; Bs[lc + 1][lr] = v0.y;
            Bs[lc + 2][lr] = v0.z; Bs[lc + 3][lr] = v0.w;
            Bs[lc + 4][lr] = v1.x; Bs[lc + 5][lr] = v1.y;
            Bs[lc + 6][lr] = v1.z; Bs[lc + 7][lr] = v1.w;
        }
        __syncthreads();
#pragma unroll
        for (int k = 0; k < BK; k++) {   // ascending k: serial dependent FMA chain
            float a[8], b[8];
            *reinterpret_cast<float4*>(a)     = *reinterpret_cast<const float4*>(&As[k][tm]);
            *reinterpret_cast<float4*>(a + 4) = *reinterpret_cast<const float4*>(&As[k][tm + 4]);
            *reinterpret_cast<float4*>(b)     = *reinterpret_cast<const float4*>(&Bs[k][tn]);
            *reinterpret_cast<float4*>(b + 4) = *reinterpret_cast<const float4*>(&Bs[k][tn + 4]);
            u64 b2[4];
            b2[0] = pack2(b[0], b[1]);
            b2[1] = pack2(b[2], b[3]);
            b2[2] = pack2(b[4], b[5]);
            b2[3] = pack2(b[6], b[7]);
#pragma unroll
            for (int i = 0; i < 8; i++) {
                u64 a2 = pack2(a[i], a[i]);
#pragma unroll
                for (int j2 = 0; j2 < 4; j2++)
                    fma2(acc2[i][j2], a2, b2[j2], acc2[i][j2]);
            }
        }
        __syncthreads();
        if (((t + 1) % KC_TILES) == 0) {   // panel boundary: fold partial into C
#pragma unroll
            for (int i = 0; i < 8; i++)
#pragma unroll
                for (int j2 = 0; j2 < 4; j2++) {
                    float lo, hi;
                    unpack2(acc2[i][j2], lo, hi);
                    int e = i * 8 + j2 * 2;
                    Csm[e * 256 + tid]       = __fadd_rn(Csm[e * 256 + tid], lo);
                    Csm[(e + 1) * 256 + tid] = __fadd_rn(Csm[(e + 1) * 256 + tid], hi);
                    acc2[i][j2] = 0ull;
                }
        }
    }
    // final (possibly partial) panel fold — exact no-op if acc == 0
#pragma unroll
    for (int i = 0; i < 8; i++)
#pragma unroll
        for (int j2 = 0; j2 < 4; j2++) {
            float lo, hi;
            unpack2(acc2[i][j2], lo, hi);
            int e = i * 8 + j2 * 2;
            Csm[e * 256 + tid]       = __fadd_rn(Csm[e * 256 + tid], lo);
            Csm[(e + 1) * 256 + tid] = __fadd_rn(Csm[(e + 1) * 256 + tid], hi);
        }

    if (EPI == 0) {
        float as = act_s[0];
        float bsv[8], bbv[8];
#pragma unroll
        for (int j = 0; j < 8; j++) {
            bsv[j] = bns[bn0 + tn + j];
            bbv[j] = bnb[bn0 + tn + j];
        }
#pragma unroll
        for (int i = 0; i < 8; i++) {
            float pk[8];
#pragma unroll
            for (int j = 0; j < 8; j++) {
                float c   = Csm[(i * 8 + j) * 256 + tid];
                float m   = __fmul_rn(c, bsv[j]);
                float pre = __fadd_rn(m, bbv[j]);
                float t   = __fdiv_rn(fmaxf(pre, 0.0f), as);
                t = fminf(fmaxf(t, 0.0f), 15.0f);
                pk[j] = __fmul_rn(rintf(t), as);
            }
            float4* dst = reinterpret_cast<float4*>(
                outF + (size_t)(bm0 + tm + i) * H_DIM + bn0 + tn);
            dst[0] = *reinterpret_cast<const float4*>(pk);
            dst[1] = *reinterpret_cast<const float4*>(pk + 4);
        }
    } else {
#pragma unroll
        for (int i = 0; i < 8; i++) {
            size_t row = (size_t)(bm0 + tm + i);
#pragma unroll
            for (int j = 0; j < 8; j++) {
                int col = bn0 + tn + j;
                if (col < C_DIM) outF[row * C_DIM + col] = Csm[(i * 8 + j) * 256 + tid];
            }
        }
    }
}

// ---------------- launch --------------------------------------------------
extern "C" void kernel_launch(void* const* d_in, const int* in_sizes, int n_in,
                              void* d_out, int out_size) {
    (void)in_sizes; (void)n_in; (void)out_size;
    const float* x    = (const float*)d_in[0];
    const float* w1   = (const float*)d_in[1];
    const float* w2   = (const float*)d_in[2];
    const float* w3   = (const float*)d_in[3];
    const float* w4   = (const float*)d_in[4];
    const float* bns1 = (const float*)d_in[5];
    const float* bnb1 = (const float*)d_in[6];
    const float* bns2 = (const float*)d_in[7];
    const float* bnb2 = (const float*)d_in[8];
    const float* bns3 = (const float*)d_in[9];
    const float* bnb3 = (const float*)d_in[10];
    const float* as1  = (const float*)d_in[11];
    const float* as2  = (const float*)d_in[12];
    const float* as3  = (const float*)d_in[13];
    float* out = (float*)d_out;

    float *w1q, *w2q, *w3q, *w4q, *h1, *h2;
    cudaGetSymbolAddress((void**)&w1q, g_w1q);
    cudaGetSymbolAddress((void**)&w2q, g_w2q);
    cudaGetSymbolAddress((void**)&w3q, g_w3q);
    cudaGetSymbolAddress((void**)&w4q, g_w4q);
    cudaGetSymbolAddress((void**)&h1,  g_h1);
    cudaGetSymbolAddress((void**)&h2,  g_h2);

    const int SMEM = (2 * BK * 128 + 64 * 256) * sizeof(float);  // 80 KB
    cudaFuncSetAttribute(k_gemm<0>, cudaFuncAttributeMaxDynamicSharedMemorySize, SMEM);
    cudaFuncSetAttribute(k_gemm<1>, cudaFuncAttributeMaxDynamicSharedMemorySize, SMEM);

    k_zero_absmax<<<1, 32>>>();
    k_absmax<<<1024, 256>>>(w1, (size_t)H_DIM * D_DIM, 0);
    k_absmax<<<1024, 256>>>(w2, (size_t)H_DIM * H_DIM, 1);
    k_absmax<<<1024, 256>>>(w3, (size_t)H_DIM * H_DIM, 2);
    k_absmax<<<1024, 256>>>(w4, (size_t)C_DIM * H_DIM, 3);

    k_quant<<<4096, 256>>>(w1, w1q, (size_t)H_DIM * D_DIM, (size_t)H_DIM * D_DIM, 0);
    k_quant<<<8192, 256>>>(w2, w2q, (size_t)H_DIM * H_DIM, (size_t)H_DIM * H_DIM, 1);
    k_quant<<<8192, 256>>>(w3, w3q, (size_t)H_DIM * H_DIM, (size_t)H_DIM * H_DIM, 2);
    k_quant<<<2048, 256>>>(w4, w4q, (size_t)C_DIM * H_DIM, (size_t)C_PAD * H_DIM, 3);

    dim3 gHH(H_DIM / 128, B_DIM / 128);
    dim3 gC (C_PAD / 128, B_DIM / 128);
    k_gemm<0><<<gHH, 256, SMEM>>>(x,  w1q, D_DIM, h1,  bns1, bnb1, as1);
    k_gemm<0><<<gHH, 256, SMEM>>>(h1, w2q, H_DIM, h2,  bns2, bnb2, as2);
    k_gemm<0><<<gHH, 256, SMEM>>>(h2, w3q, H_DIM, h1,  bns3, bnb3, as3);
    k_gemm<1><<<gC,  256, SMEM>>>(h1, w4q, H_DIM, out, nullptr, nullptr, nullptr);
}